// round 2
// baseline (speedup 1.0000x reference)
#include <cuda_runtime.h>
#include <cstdint>

#define Bsz 512
#define Nn  8192
#define CH  16
#define NC  (Nn / CH)

// Scratch ([i][b] layouts for coalesced scan access; static __device__ per harness rules)
__device__ float2 g_lplq[(size_t)Bsz * Nn];   // (lp_i, lq_i) transposed [i][b]
__device__ float  g_uT  [(size_t)Bsz * Nn];   // noise transposed [i][b]
__device__ int    g_sel [Bsz];

__device__ __forceinline__ float neg_inf_f() { return __int_as_float(0xff800000); }

// log1mexp(x) = log(1 - e^x), x <= 0, matching the reference's branch structure
__device__ __forceinline__ float log1mexp_f(float x) {
    return (x > -0.69314718f) ? logf(-expm1f(x)) : log1pf(-expf(x));
}

#define BAR_ARRIVE(id) asm volatile("bar.arrive %0, 64;" :: "r"(id) : "memory")
#define BAR_SYNC(id)   asm volatile("bar.sync %0, 64;"   :: "r"(id) : "memory")

// ---------------------------------------------------------------------------
// Kernel 1: elementwise lp/lq from logits, transpose lp/lq and noise to [i][b]
// ---------------------------------------------------------------------------
__global__ void k_prep(const float* __restrict__ logits,
                       const float* __restrict__ noise) {
    __shared__ float2 tile[32][33];
    __shared__ float  tu  [32][33];
    const int tx = threadIdx.x, ty = threadIdx.y;
    const int i0 = blockIdx.x * 32;   // item index base
    const int b0 = blockIdx.y * 32;   // row index base

    #pragma unroll
    for (int r = 0; r < 4; r++) {
        const int b = b0 + ty + r * 8;
        const int i = i0 + tx;
        const size_t src = (size_t)b * Nn + i;
        const float z = logits[src];
        // jax.nn.log_sigmoid(z) = -(max(-z,0) + log1p(exp(-|z|)))
        const float sp = fmaxf(-z, 0.0f) + log1pf(expf(-fabsf(z)));
        const float lp = fminf(-sp, -1e-7f);
        const float lq = log1mexp_f(lp);
        tile[ty + r * 8][tx] = make_float2(lp, lq);
        tu  [ty + r * 8][tx] = noise[src];
    }
    __syncthreads();
    #pragma unroll
    for (int r = 0; r < 4; r++) {
        const int i = i0 + ty + r * 8;
        const int b = b0 + tx;
        const size_t dst = (size_t)i * Bsz + b;
        g_lplq[dst] = tile[tx][ty + r * 8];
        g_uT[dst]   = tu  [tx][ty + r * 8];
    }
}

// ---------------------------------------------------------------------------
// Kernel 2 (fused): warp 0 = sequential forward DP per row (the irreducible
// latency chain); warp 1 = reverse-pass decision consumer, fed via a
// double-buffered SMEM ring with named barriers. With K=1, the selected item
// is the MAX index i with u_i < sigmoid(p_i - q_i); thresholds after the
// success are exactly 0, so no reverse scan is needed.
// Barrier ids: full[p] = p (0,1); free[p] = 2+p.
// ---------------------------------------------------------------------------
__global__ void __launch_bounds__(64, 1) k_scan_fused() {
    __shared__ float2 ring[2][CH][32];
    const int lane = threadIdx.x & 31;
    const int w    = threadIdx.x >> 5;
    const int b    = blockIdx.x * 32 + lane;

    if (w == 0) {
        // ---------------- producer: the serial DP chain ----------------
        float A0 = 0.0f;
        float A1 = neg_inf_f();
        float2 bufA[CH], bufB[CH];

        #pragma unroll
        for (int j = 0; j < CH; j++) bufA[j] = g_lplq[(size_t)j * Bsz + b];
        #pragma unroll
        for (int j = 0; j < CH; j++) bufB[j] = g_lplq[(size_t)(CH + j) * Bsz + b];

        for (int c = 0; c < NC; c += 2) {
            // chunk c (parity 0)
            if (c >= 2) BAR_SYNC(2 + 0);
            #pragma unroll
            for (int j = 0; j < CH; j++) {
                const float lp = bufA[j].x, lq = bufA[j].y;
                const float x1 = A0 + lp;
                const float x2 = A1 + lq;
                const float m  = fmaxf(x1, x2);
                const float dd = x1 - x2;            // +inf at step 1 (A1=-inf): exp->0, ok
                const float t  = log1pf(expf(-fabsf(dd)));
                A1 = m + t;
                A0 = A0 + lq;
                ring[0][j][lane] = make_float2(x1, A1);
            }
            BAR_ARRIVE(0);
            if (c + 2 < NC) {
                #pragma unroll
                for (int j = 0; j < CH; j++)
                    bufA[j] = g_lplq[(size_t)((c + 2) * CH + j) * Bsz + b];
            }
            // chunk c+1 (parity 1)
            if (c >= 2) BAR_SYNC(2 + 1);
            #pragma unroll
            for (int j = 0; j < CH; j++) {
                const float lp = bufB[j].x, lq = bufB[j].y;
                const float x1 = A0 + lp;
                const float x2 = A1 + lq;
                const float m  = fmaxf(x1, x2);
                const float dd = x1 - x2;
                const float t  = log1pf(expf(-fabsf(dd)));
                A1 = m + t;
                A0 = A0 + lq;
                ring[1][j][lane] = make_float2(x1, A1);
            }
            BAR_ARRIVE(1);
            if (c + 3 < NC) {
                #pragma unroll
                for (int j = 0; j < CH; j++)
                    bufB[j] = g_lplq[(size_t)((c + 3) * CH + j) * Bsz + b];
            }
        }
    } else {
        // ---------------- consumer: decisions (off the chain's SMSP) ----
        int sel = -1;
        float uu[CH];
        #pragma unroll
        for (int j = 0; j < CH; j++) uu[j] = g_uT[(size_t)j * Bsz + b];

        for (int c = 0; c < NC; c++) {
            const int p = c & 1;
            BAR_SYNC(p);
            float2 xa[CH];
            #pragma unroll
            for (int j = 0; j < CH; j++) xa[j] = ring[p][j][lane];
            BAR_ARRIVE(2 + p);

            float un[CH];
            if (c + 1 < NC) {
                #pragma unroll
                for (int j = 0; j < CH; j++)
                    un[j] = g_uT[(size_t)((c + 1) * CH + j) * Bsz + b];
            }
            #pragma unroll
            for (int j = 0; j < CH; j++) {
                float r = xa[j].x - xa[j].y;          // (A0_{i-1}+lp_i) - A1_i, ref op order
                r = fminf(r, 0.0f);
                const float q = log1mexp_f(r);
                const float d = r - q;
                const float t = 1.0f / (1.0f + expf(-d));   // sigmoid
                if (uu[j] < t) sel = c * CH + j;
            }
            #pragma unroll
            for (int j = 0; j < CH; j++) uu[j] = un[j];
        }
        g_sel[b] = sel;
    }
}

// ---------------------------------------------------------------------------
// Kernel 3: write output (one 1 per row at the selected index, else 0), f4
// ---------------------------------------------------------------------------
__global__ void k_write(float4* __restrict__ out) {
    const int e  = blockIdx.x * blockDim.x + threadIdx.x;  // over Bsz*Nn/4
    const int b  = e >> 11;          // 2048 float4 per row
    const int i  = (e & 2047) * 4;
    const int s  = g_sel[b];
    float4 v;
    v.x = (i     == s) ? 1.0f : 0.0f;
    v.y = (i + 1 == s) ? 1.0f : 0.0f;
    v.z = (i + 2 == s) ? 1.0f : 0.0f;
    v.w = (i + 3 == s) ? 1.0f : 0.0f;
    out[e] = v;
}

extern "C" void kernel_launch(void* const* d_in, const int* in_sizes, int n_in,
                              void* d_out, int out_size) {
    const float* logits = (const float*)d_in[0];
    const float* noise  = (const float*)d_in[1];
    float4* out = (float4*)d_out;

    dim3 b1(32, 8), g1(Nn / 32, Bsz / 32);
    k_prep<<<g1, b1>>>(logits, noise);
    k_scan_fused<<<Bsz / 32, 64>>>();
    k_write<<<(Bsz * Nn / 4) / 256, 256>>>(out);
}

// round 3
// speedup vs baseline: 2.1651x; 2.1651x over previous
#include <cuda_runtime.h>
#include <cstdint>

#define Bsz 512
#define Nn  8192
#define CH  16
#define NC  (Nn / CH)

// Scratch ([i][b] layouts for coalesced access; static __device__ per harness rules)
__device__ float2 g_lplq[(size_t)Bsz * Nn];   // (lp_i, lq_i) transposed [i][b]
__device__ float  g_uT  [(size_t)Bsz * Nn];   // noise transposed [i][b]
__device__ float  g_r   [(size_t)Bsz * Nn];   // r_i = x1_i - A1_i, [i][b]
__device__ int    g_sel [Bsz];

__device__ __forceinline__ float neg_inf_f() { return __int_as_float(0xff800000); }

// log1mexp(x) = log(1 - e^x), x <= 0, matching the reference's branch structure
__device__ __forceinline__ float log1mexp_f(float x) {
    return (x > -0.69314718f) ? logf(-expm1f(x)) : log1pf(-expf(x));
}

// ---------------------------------------------------------------------------
// Kernel 1: elementwise lp/lq from logits, transpose lp/lq and noise to [i][b]
// ---------------------------------------------------------------------------
__global__ void k_prep(const float* __restrict__ logits,
                       const float* __restrict__ noise) {
    __shared__ float2 tile[32][33];
    __shared__ float  tu  [32][33];
    const int tx = threadIdx.x, ty = threadIdx.y;
    const int i0 = blockIdx.x * 32;   // item index base
    const int b0 = blockIdx.y * 32;   // row index base

    #pragma unroll
    for (int r = 0; r < 4; r++) {
        const int b = b0 + ty + r * 8;
        const int i = i0 + tx;
        const size_t src = (size_t)b * Nn + i;
        const float z = logits[src];
        // jax.nn.log_sigmoid(z) = -(max(-z,0) + log1p(exp(-|z|)))
        const float sp = fmaxf(-z, 0.0f) + log1pf(expf(-fabsf(z)));
        const float lp = fminf(-sp, -1e-7f);
        const float lq = log1mexp_f(lp);
        tile[ty + r * 8][tx] = make_float2(lp, lq);
        tu  [ty + r * 8][tx] = noise[src];
    }
    __syncthreads();
    #pragma unroll
    for (int r = 0; r < 4; r++) {
        const int i = i0 + ty + r * 8;
        const int b = b0 + tx;
        const size_t dst = (size_t)i * Bsz + b;
        g_lplq[dst] = tile[tx][ty + r * 8];
        g_uT[dst]   = tu  [tx][ty + r * 8];
    }
}

// Tiny helpers: reset g_sel (graph replays must be deterministic) + ncu slot pad
__global__ void k_reset() { g_sel[threadIdx.x] = -1; }
__global__ void k_pad() {}

// ---------------------------------------------------------------------------
// Kernel 2: sequential forward DP per row (the irreducible latency chain).
// A0' = A0 + lq   (logaddexp_c with one -inf arm)
// A1' = max(x1,x2) + log1p(exp(-|x1-x2|)), x1 = A0+lp, x2 = A1+lq
// Emits only r_i = x1_i - A1_i (exactly what the decide pass consumes first),
// so the reverse pass is fully parallel and the per-item store is STG.32.
// ---------------------------------------------------------------------------
__global__ void __launch_bounds__(32, 1) k_scan() {
    const int b = blockIdx.x * 32 + threadIdx.x;
    float A0 = 0.0f;
    float A1 = neg_inf_f();

    float2 bufA[CH], bufB[CH];
    #pragma unroll
    for (int j = 0; j < CH; j++) bufA[j] = g_lplq[(size_t)j * Bsz + b];
    #pragma unroll
    for (int j = 0; j < CH; j++) bufB[j] = g_lplq[(size_t)(CH + j) * Bsz + b];

    for (int c = 0; c < NC; c += 2) {
        #pragma unroll
        for (int j = 0; j < CH; j++) {
            const float lp = bufA[j].x, lq = bufA[j].y;
            const float x1 = A0 + lp;
            const float x2 = A1 + lq;
            const float m  = fmaxf(x1, x2);
            const float dd = x1 - x2;            // +inf at step 1 (A1=-inf): exp->0, ok
            const float t  = log1pf(expf(-fabsf(dd)));
            A1 = m + t;
            A0 = A0 + lq;
            g_r[(size_t)(c * CH + j) * Bsz + b] = x1 - A1;
        }
        if (c + 2 < NC) {
            #pragma unroll
            for (int j = 0; j < CH; j++)
                bufA[j] = g_lplq[(size_t)((c + 2) * CH + j) * Bsz + b];
        }
        #pragma unroll
        for (int j = 0; j < CH; j++) {
            const float lp = bufB[j].x, lq = bufB[j].y;
            const float x1 = A0 + lp;
            const float x2 = A1 + lq;
            const float m  = fmaxf(x1, x2);
            const float dd = x1 - x2;
            const float t  = log1pf(expf(-fabsf(dd)));
            A1 = m + t;
            A0 = A0 + lq;
            g_r[(size_t)((c + 1) * CH + j) * Bsz + b] = x1 - A1;
        }
        if (c + 3 < NC) {
            #pragma unroll
            for (int j = 0; j < CH; j++)
                bufB[j] = g_lplq[(size_t)((c + 3) * CH + j) * Bsz + b];
        }
    }
}

// ---------------------------------------------------------------------------
// Kernel 3: parallel reverse-pass decisions. With K=1, j stays at its initial
// value until the single success (thresholds after it are exactly 0), so the
// selected item is the MAX index i with u_i < sigmoid(p_i - q_i).
// ---------------------------------------------------------------------------
__global__ void k_decide() {
    const int e = blockIdx.x * blockDim.x + threadIdx.x;  // e = i*Bsz + b
    const int b = e & (Bsz - 1);
    const int i = e >> 9;
    float r = g_r[e];                 // (A0_{i-1} + lp_i) - A1_i, ref op order
    r = fminf(r, 0.0f);
    const float q = log1mexp_f(r);
    const float d = r - q;
    const float t = 1.0f / (1.0f + expf(-d));  // sigmoid; d=+inf -> 1
    const float u = g_uT[e];
    if (u < t) atomicMax(&g_sel[b], i);
}

// ---------------------------------------------------------------------------
// Kernel 4: write output (one 1 per row at the selected index, else 0), f4
// ---------------------------------------------------------------------------
__global__ void k_write(float4* __restrict__ out) {
    const int e  = blockIdx.x * blockDim.x + threadIdx.x;  // over Bsz*Nn/4
    const int b  = e >> 11;          // 2048 float4 per row
    const int i  = (e & 2047) * 4;
    const int s  = g_sel[b];
    float4 v;
    v.x = (i     == s) ? 1.0f : 0.0f;
    v.y = (i + 1 == s) ? 1.0f : 0.0f;
    v.z = (i + 2 == s) ? 1.0f : 0.0f;
    v.w = (i + 3 == s) ? 1.0f : 0.0f;
    out[e] = v;
}

extern "C" void kernel_launch(void* const* d_in, const int* in_sizes, int n_in,
                              void* d_out, int out_size) {
    const float* logits = (const float*)d_in[0];
    const float* noise  = (const float*)d_in[1];
    float4* out = (float4*)d_out;

    dim3 b1(32, 8), g1(Nn / 32, Bsz / 32);
    k_prep<<<g1, b1>>>(logits, noise);
    k_reset<<<1, Bsz>>>();            // also pads ncu launch slot #4
    k_pad<<<1, 32>>>();               // pads slot #5 so k_scan lands on #6 (-s 5 -c 1)
    k_scan<<<Bsz / 32, 32>>>();
    k_decide<<<(Bsz * Nn) / 256, 256>>>();
    k_write<<<(Bsz * Nn / 4) / 256, 256>>>(out);
}

// round 4
// speedup vs baseline: 2.3040x; 1.0641x over previous
#include <cuda_runtime.h>
#include <cstdint>

#define Bsz 512
#define Nn  8192
#define CH  16
#define NC  (Nn / CH)

// Scratch (static __device__ per harness rules)
__device__ float2 g_lplq[(size_t)Bsz * Nn];   // (lp_i, lq_i) transposed [i][b]
__device__ float  g_r   [(size_t)Bsz * Nn];   // r_i = x1_i - A1_i, layout [b][i]
__device__ int    g_sel [Bsz];

__device__ __forceinline__ float neg_inf_f() { return __int_as_float(0xff800000); }

// log1mexp(x) = log(1 - e^x), x <= 0, matching the reference's branch structure
__device__ __forceinline__ float log1mexp_f(float x) {
    return (x > -0.69314718f) ? logf(-expm1f(x)) : log1pf(-expf(x));
}

// ---------------------------------------------------------------------------
// Kernel 1: elementwise lp/lq from logits, transposed to [i][b]
// ---------------------------------------------------------------------------
__global__ void k_prep(const float* __restrict__ logits) {
    __shared__ float2 tile[32][33];
    const int tx = threadIdx.x, ty = threadIdx.y;
    const int i0 = blockIdx.x * 32;   // item index base
    const int b0 = blockIdx.y * 32;   // row index base

    #pragma unroll
    for (int r = 0; r < 4; r++) {
        const int b = b0 + ty + r * 8;
        const int i = i0 + tx;
        const float z = logits[(size_t)b * Nn + i];
        // jax.nn.log_sigmoid(z) = -(max(-z,0) + log1p(exp(-|z|)))
        const float sp = fmaxf(-z, 0.0f) + log1pf(expf(-fabsf(z)));
        const float lp = fminf(-sp, -1e-7f);
        const float lq = log1mexp_f(lp);
        tile[ty + r * 8][tx] = make_float2(lp, lq);
    }
    __syncthreads();
    #pragma unroll
    for (int r = 0; r < 4; r++) {
        const int i = i0 + ty + r * 8;
        const int b = b0 + tx;
        g_lplq[(size_t)i * Bsz + b] = tile[tx][ty + r * 8];
    }
}

// reset g_sel each launch (graph replays must be deterministic)
__global__ void k_reset() { g_sel[threadIdx.x] = -1; }

// ---------------------------------------------------------------------------
// Kernel 2: sequential forward DP per row (the irreducible latency chain).
// A0' = A0 + lq   (logaddexp_c with one -inf arm)
// A1' = max(x1,x2) + log1p(exp(-|x1-x2|)), x1 = A0+lp, x2 = A1+lq
// Emits r_i = x1_i - A1_i in [b][i] layout (float4 stores, off-chain).
// ---------------------------------------------------------------------------
__global__ void __launch_bounds__(32, 1) k_scan() {
    const int b = blockIdx.x * 32 + threadIdx.x;
    float4* __restrict__ rrow = (float4*)(g_r + (size_t)b * Nn);
    float A0 = 0.0f;
    float A1 = neg_inf_f();

    float2 bufA[CH], bufB[CH];
    #pragma unroll
    for (int j = 0; j < CH; j++) bufA[j] = g_lplq[(size_t)j * Bsz + b];
    #pragma unroll
    for (int j = 0; j < CH; j++) bufB[j] = g_lplq[(size_t)(CH + j) * Bsz + b];

    for (int c = 0; c < NC; c += 2) {
        {
            float4 acc;
            #pragma unroll
            for (int j = 0; j < CH; j++) {
                const float lp = bufA[j].x, lq = bufA[j].y;
                const float x1 = A0 + lp;
                const float x2 = A1 + lq;
                const float m  = fmaxf(x1, x2);
                const float dd = x1 - x2;         // +inf at step 1 (A1=-inf): exp->0, ok
                const float t  = log1pf(expf(-fabsf(dd)));
                A1 = m + t;
                A0 = A0 + lq;
                const float rv = x1 - A1;
                if ((j & 3) == 0) acc.x = rv;
                else if ((j & 3) == 1) acc.y = rv;
                else if ((j & 3) == 2) acc.z = rv;
                else { acc.w = rv; rrow[(c * CH + j) >> 2] = acc; }
            }
        }
        if (c + 2 < NC) {
            #pragma unroll
            for (int j = 0; j < CH; j++)
                bufA[j] = g_lplq[(size_t)((c + 2) * CH + j) * Bsz + b];
        }
        {
            float4 acc;
            #pragma unroll
            for (int j = 0; j < CH; j++) {
                const float lp = bufB[j].x, lq = bufB[j].y;
                const float x1 = A0 + lp;
                const float x2 = A1 + lq;
                const float m  = fmaxf(x1, x2);
                const float dd = x1 - x2;
                const float t  = log1pf(expf(-fabsf(dd)));
                A1 = m + t;
                A0 = A0 + lq;
                const float rv = x1 - A1;
                if ((j & 3) == 0) acc.x = rv;
                else if ((j & 3) == 1) acc.y = rv;
                else if ((j & 3) == 2) acc.z = rv;
                else { acc.w = rv; rrow[((c + 1) * CH + j) >> 2] = acc; }
            }
        }
        if (c + 3 < NC) {
            #pragma unroll
            for (int j = 0; j < CH; j++)
                bufB[j] = g_lplq[(size_t)((c + 3) * CH + j) * Bsz + b];
        }
    }
}

// ---------------------------------------------------------------------------
// Kernel 3: parallel decisions. With K=1, the selected item is the MAX index
// i with u_i < sigmoid(p_i - q_i) (thresholds after the success are exactly 0).
// float4 per thread; one warp covers 128 consecutive items of one row ->
// warp-reduce the max, single atomicMax per warp.
// ---------------------------------------------------------------------------
__global__ void k_decide(const float* __restrict__ noise) {
    const int e  = blockIdx.x * blockDim.x + threadIdx.x;   // over Bsz*Nn/4
    const int b  = e >> 11;                                  // 2048 float4 per row
    const int i0 = (e & 2047) * 4;
    const float4 rv = ((const float4*)g_r)[e];
    const float4 uv = ((const float4*)noise)[e];

    int sel = -1;
    #pragma unroll
    for (int j = 0; j < 4; j++) {
        float r = (j == 0) ? rv.x : (j == 1) ? rv.y : (j == 2) ? rv.z : rv.w;
        const float u = (j == 0) ? uv.x : (j == 1) ? uv.y : (j == 2) ? uv.z : uv.w;
        r = fminf(r, 0.0f);                       // clamp, ref op order
        const float q = log1mexp_f(r);
        const float d = r - q;
        const float t = 1.0f / (1.0f + expf(-d)); // sigmoid; d=+inf -> 1
        if (u < t) sel = i0 + j;
    }
    // warp max (all lanes share the same row b)
    #pragma unroll
    for (int s = 16; s > 0; s >>= 1)
        sel = max(sel, __shfl_xor_sync(0xffffffffu, sel, s));
    if ((threadIdx.x & 31) == 0 && sel >= 0) atomicMax(&g_sel[b], sel);
}

// ---------------------------------------------------------------------------
// Kernel 4: write output (one 1 per row at the selected index, else 0), f4
// ---------------------------------------------------------------------------
__global__ void k_write(float4* __restrict__ out) {
    const int e = blockIdx.x * blockDim.x + threadIdx.x;   // over Bsz*Nn/4
    const int b = e >> 11;
    const int i = (e & 2047) * 4;
    const int s = g_sel[b];
    float4 v;
    v.x = (i     == s) ? 1.0f : 0.0f;
    v.y = (i + 1 == s) ? 1.0f : 0.0f;
    v.z = (i + 2 == s) ? 1.0f : 0.0f;
    v.w = (i + 3 == s) ? 1.0f : 0.0f;
    out[e] = v;
}

extern "C" void kernel_launch(void* const* d_in, const int* in_sizes, int n_in,
                              void* d_out, int out_size) {
    const float* logits = (const float*)d_in[0];
    const float* noise  = (const float*)d_in[1];
    float4* out = (float4*)d_out;

    dim3 b1(32, 8), g1(Nn / 32, Bsz / 32);
    k_prep<<<g1, b1>>>(logits);
    k_reset<<<1, Bsz>>>();
    k_scan<<<Bsz / 32, 32>>>();
    k_decide<<<(Bsz * Nn / 4) / 256, 256>>>(noise);   // ncu slot #6 this round
    k_write<<<(Bsz * Nn / 4) / 256, 256>>>(out);
}